// round 5
// baseline (speedup 1.0000x reference)
#include <cuda_runtime.h>
#include <cooperative_groups.h>
#include <cstdint>
#include <cstddef>

namespace cg = cooperative_groups;

#define BSZ 640
#define TSTEPS 160
#define FIN 80
#define HID 768
#define PROJ 256
#define NG 3072
#define EMB 256
#define RTHR 384
#define CNSEQ 20          // sequences per 4-CTA cluster
#define UPC 192           // hidden units per CTA

// ---- device scratch ----
__device__ float  g_pre[(size_t)BSZ * TSTEPS * NG];
__device__ float  g_seq[(size_t)BSZ * TSTEPS * PROJ];
__device__ float2 g_whhT[3 * 128 * 4 * HID];
__device__ float2 g_whrT[3 * 384 * PROJ];
__device__ float  g_wlinT[PROJ * EMB];

typedef unsigned long long ull;

__device__ __forceinline__ void fma2(ull& d, ull a, ull b) {
    asm("fma.rn.f32x2 %0, %1, %2, %0;" : "+l"(d) : "l"(a), "l"(b));
}
__device__ __forceinline__ ull pack2(float x, float y) {
    ull r; asm("mov.b64 %0, {%1, %2};" : "=l"(r) : "f"(x), "f"(y)); return r;
}
__device__ __forceinline__ float2 unpack2(ull v) {
    float2 r; asm("mov.b64 {%0, %1}, %2;" : "=f"(r.x), "=f"(r.y) : "l"(v)); return r;
}
__device__ __forceinline__ float sigm_f(float x) { return 1.f / (1.f + __expf(-x)); }
__device__ __forceinline__ float tanh_f(float x) { return 1.f - 2.f / (__expf(2.f * x) + 1.f); }

// ---- weight re-layout (same layouts as R3; 4-CTA kernel slices them by rank) ----
__global__ void prep_weights(const float* __restrict__ W0, const float* __restrict__ W1,
                             const float* __restrict__ W2,
                             const float* __restrict__ R0, const float* __restrict__ R1,
                             const float* __restrict__ R2,
                             const float* __restrict__ L) {
    const int NWHH = 3 * 128 * 4 * HID;
    const int NWHR = 3 * 384 * PROJ;
    const int NWL  = PROJ * EMB;
    const int total = NWHH + NWHR + NWL;
    for (int i = blockIdx.x * blockDim.x + threadIdx.x; i < total; i += gridDim.x * blockDim.x) {
        if (i < NWHH) {
            int l = i / (128 * 4 * HID);
            int r = i % (128 * 4 * HID);
            int u = r % HID;
            int g = (r / HID) % 4;
            int kp = r / (4 * HID);
            const float* W = (l == 0) ? W0 : (l == 1) ? W1 : W2;
            size_t j = (size_t)(g * HID + u) * PROJ;
            g_whhT[i] = make_float2(W[j + 2 * kp], W[j + 2 * kp + 1]);
        } else if (i < NWHH + NWHR) {
            int i2 = i - NWHH;
            int l = i2 / (384 * PROJ);
            int r = i2 % (384 * PROJ);
            int p = r % PROJ;
            int up = r / PROJ;
            const float* R = (l == 0) ? R0 : (l == 1) ? R1 : R2;
            g_whrT[i2] = make_float2(R[(size_t)p * HID + 2 * up], R[(size_t)p * HID + 2 * up + 1]);
        } else {
            int i3 = i - NWHH - NWHR;
            int e = i3 % EMB, p = i3 / EMB;
            g_wlinT[i3] = L[(size_t)e * PROJ + p];
        }
    }
}

// ---- input GEMM (unchanged) ----
template <int K>
__global__ __launch_bounds__(256) void pre_gemm_kernel(const float* __restrict__ xin, int use_seq,
                                                       const float* __restrict__ W,
                                                       const float* __restrict__ bih,
                                                       const float* __restrict__ bhh) {
    const float* A = use_seq ? g_seq : xin;
    __shared__ __align__(16) float As[8][128];
    __shared__ __align__(16) float Bs[8][128];
    const int tid = threadIdx.x;
    const int n0 = blockIdx.x * 128;
    const int m0 = blockIdx.y * 128;
    const int lr = tid >> 1;
    const int lk = (tid & 1) * 4;
    const float* aptr = A + (size_t)(m0 + lr) * K + lk;
    const float* wptr = W + (size_t)(n0 + lr) * K + lk;
    const int tx = tid & 15, ty = tid >> 4;

    ull acc[8][4];
#pragma unroll
    for (int m = 0; m < 8; ++m)
#pragma unroll
        for (int n = 0; n < 4; ++n) acc[m][n] = 0ULL;

    float4 aReg = *(const float4*)aptr;
    float4 bReg = *(const float4*)wptr;
    const int nch = K / 8;

    for (int ch = 0;; ++ch) {
        As[lk + 0][lr] = aReg.x; As[lk + 1][lr] = aReg.y; As[lk + 2][lr] = aReg.z; As[lk + 3][lr] = aReg.w;
        Bs[lk + 0][lr] = bReg.x; Bs[lk + 1][lr] = bReg.y; Bs[lk + 2][lr] = bReg.z; Bs[lk + 3][lr] = bReg.w;
        __syncthreads();
        if (ch + 1 < nch) {
            aptr += 8; wptr += 8;
            aReg = *(const float4*)aptr;
            bReg = *(const float4*)wptr;
        }
#pragma unroll
        for (int k = 0; k < 8; ++k) {
            float4 alo = *(const float4*)&As[k][ty * 8];
            float4 ahi = *(const float4*)&As[k][ty * 8 + 4];
            ulonglong2 bl = *(const ulonglong2*)&Bs[k][tx * 8];
            ulonglong2 bh = *(const ulonglong2*)&Bs[k][tx * 8 + 4];
            ull ap[8];
            ap[0] = pack2(alo.x, alo.x); ap[1] = pack2(alo.y, alo.y);
            ap[2] = pack2(alo.z, alo.z); ap[3] = pack2(alo.w, alo.w);
            ap[4] = pack2(ahi.x, ahi.x); ap[5] = pack2(ahi.y, ahi.y);
            ap[6] = pack2(ahi.z, ahi.z); ap[7] = pack2(ahi.w, ahi.w);
#pragma unroll
            for (int m = 0; m < 8; ++m) {
                fma2(acc[m][0], ap[m], bl.x);
                fma2(acc[m][1], ap[m], bl.y);
                fma2(acc[m][2], ap[m], bh.x);
                fma2(acc[m][3], ap[m], bh.y);
            }
        }
        __syncthreads();
        if (ch + 1 >= nch) break;
    }

    const int col = n0 + tx * 8;
    float bs[8];
#pragma unroll
    for (int i = 0; i < 8; ++i) bs[i] = bih[col + i] + bhh[col + i];
#pragma unroll
    for (int m = 0; m < 8; ++m) {
        const size_t row = (size_t)m0 + ty * 8 + m;
        float* cp = g_pre + row * NG + col;
        float2 v0 = unpack2(acc[m][0]), v1 = unpack2(acc[m][1]);
        float2 v2 = unpack2(acc[m][2]), v3 = unpack2(acc[m][3]);
        *(float4*)cp       = make_float4(v0.x + bs[0], v0.y + bs[1], v1.x + bs[2], v1.y + bs[3]);
        *(float4*)(cp + 4) = make_float4(v2.x + bs[4], v2.y + bs[5], v3.x + bs[6], v3.y + bs[7]);
    }
}

// ---- recurrent: 4-CTA cluster; CTA owns 192 units; proj k-split local; partial reduce via DSMEM ----
#define HROW 258   // padded h row (bank-conflict-free for paired-lane reads)

__global__ __launch_bounds__(RTHR, 1) __cluster_dims__(4, 1, 1)
void lstm_layer_cluster4(int layer) {
    cg::cluster_group clu = cg::this_cluster();
    const int rank = (int)clu.block_rank();
    const int t = threadIdx.x;
    const int b0 = (blockIdx.x >> 2) * CNSEQ;

    __shared__ __align__(16) float h_s[CNSEQ * HROW];    // full h, replicated per CTA (20.6 KB)
    __shared__ __align__(16) float uni[CNSEQ * PROJ];    // ht[20][192] then partial[20][256] (20 KB)

    const ull* whh_u = reinterpret_cast<const ull*>(g_whhT + (size_t)layer * (128 * 4 * HID));
    const ull* whr_u = reinterpret_cast<const ull*>(g_whrT + (size_t)layer * (384 * PROJ));

    float* peer_uni[3];
    float* peer_h[3];
    {
        int j = 0;
        for (int rr = 0; rr < 4; ++rr)
            if (rr != rank) {
                peer_uni[j] = (float*)clu.map_shared_rank(uni, rr);
                peer_h[j]   = (float*)clu.map_shared_rank(h_s, rr);
                ++j;
            }
    }

    for (int i = t; i < CNSEQ * HROW; i += RTHR) h_s[i] = 0.f;
    float c[10];
#pragma unroll
    for (int m = 0; m < 10; ++m) c[m] = 0.f;

    const int u_loc = t >> 1;         // unit within CTA [0,192)
    const int sg = t & 1;             // sequence group (0: seqs 0-9, 1: seqs 10-19)
    const int u = rank * UPC + u_loc; // global hidden unit

    clu.sync();

    for (int step = 0; step < TSTEPS; ++step) {
        // ---- gate phase: 4 gates x 10 seqs for unit u ----
        {
            ull acc[10][4];
#pragma unroll
            for (int m = 0; m < 10; ++m)
#pragma unroll
                for (int g = 0; g < 4; ++g) acc[m][g] = 0ULL;

            const ull* wk = whh_u + u;
            const float* hp = h_s + sg * 10 * HROW;
#pragma unroll 2
            for (int kp = 0; kp < 128; ++kp) {
                ull wv0 = wk[0];
                ull wv1 = wk[HID];
                ull wv2 = wk[2 * HID];
                ull wv3 = wk[3 * HID];
                ull hv[10];
#pragma unroll
                for (int m = 0; m < 10; ++m)
                    hv[m] = *reinterpret_cast<const ull*>(hp + m * HROW);
#pragma unroll
                for (int m = 0; m < 10; ++m) {
                    fma2(acc[m][0], hv[m], wv0);
                    fma2(acc[m][1], hv[m], wv1);
                    fma2(acc[m][2], hv[m], wv2);
                    fma2(acc[m][3], hv[m], wv3);
                }
                wk += 4 * HID;
                hp += 2;
            }
            const float* prebase = g_pre + ((size_t)(b0 + sg * 10) * TSTEPS + step) * NG;
#pragma unroll
            for (int m = 0; m < 10; ++m) {
                const float* pm = prebase + (size_t)m * TSTEPS * NG;
                float2 a0 = unpack2(acc[m][0]), a1 = unpack2(acc[m][1]);
                float2 a2 = unpack2(acc[m][2]), a3 = unpack2(acc[m][3]);
                float gi = a0.x + a0.y + pm[u];
                float gf = a1.x + a1.y + pm[HID + u];
                float gg = a2.x + a2.y + pm[2 * HID + u];
                float go = a3.x + a3.y + pm[3 * HID + u];
                float cn = fmaf(sigm_f(gf), c[m], sigm_f(gi) * tanh_f(gg));
                c[m] = cn;
                uni[(sg * 10 + m) * UPC + u_loc] = sigm_f(go) * tanh_f(cn);  // ht
            }
        }
        __syncthreads();

        // ---- projection partial over local 192 units (threads 0..255, p = t) ----
        ull pacc[CNSEQ];
#pragma unroll
        for (int m = 0; m < CNSEQ; ++m) pacc[m] = 0ULL;
        if (t < PROJ) {
            const ull* wr = whr_u + (size_t)(rank * 96) * PROJ + t;
            const ull* htp = reinterpret_cast<const ull*>(uni);
#pragma unroll 2
            for (int up = 0; up < 96; ++up) {
                ull wv = wr[(size_t)up * PROJ];
                ull hv[CNSEQ];
#pragma unroll
                for (int m = 0; m < CNSEQ; ++m) hv[m] = htp[m * 96 + up];
#pragma unroll
                for (int m = 0; m < CNSEQ; ++m) fma2(pacc[m], hv[m], wv);
            }
        }
        __syncthreads();   // all ht reads done; safe to overwrite uni with partials
        if (t < PROJ) {
#pragma unroll
            for (int m = 0; m < CNSEQ; ++m) {
                float2 a = unpack2(pacc[m]);
                uni[m * PROJ + t] = a.x + a.y;
            }
        }
        clu.sync();        // partials visible cluster-wide

        // ---- reduce: this CTA owns output slice [rank*64, rank*64+64) ----
        for (int idx = t; idx < CNSEQ * 32; idx += RTHR) {
            int m = idx >> 5, jp = idx & 31;
            int offf = m * PROJ + rank * 64 + 2 * jp;
            float2 s = *(const float2*)(uni + offf);
#pragma unroll
            for (int j = 0; j < 3; ++j) {
                float2 q = *(const float2*)(peer_uni[j] + offf);
                s.x += q.x; s.y += q.y;
            }
            int hoff = m * HROW + rank * 64 + 2 * jp;
            *(float2*)(h_s + hoff) = s;
#pragma unroll
            for (int j = 0; j < 3; ++j) *(float2*)(peer_h[j] + hoff) = s;
            *(float2*)(g_seq + ((size_t)(b0 + m) * TSTEPS + step) * PROJ + rank * 64 + 2 * jp) = s;
        }
        clu.sync();        // h_s consistent in all 4 CTAs before next gate phase
    }
}

// ---- head ----
__global__ __launch_bounds__(256) void head_kernel(const float* __restrict__ blin,
                                                   float* __restrict__ out) {
    __shared__ float hsh[PROJ];
    __shared__ float red[256];
    const int b = blockIdx.x, t = threadIdx.x;
    hsh[t] = g_seq[((size_t)b * TSTEPS + TSTEPS - 1) * PROJ + t];
    __syncthreads();
    float acc = 0.f;
#pragma unroll 8
    for (int p = 0; p < PROJ; ++p) acc = fmaf(hsh[p], g_wlinT[p * EMB + t], acc);
    float v = fmaxf(acc + blin[t], 0.f);
    red[t] = v * v;
    __syncthreads();
    for (int s = 128; s > 0; s >>= 1) {
        if (t < s) red[t] += red[t + s];
        __syncthreads();
    }
    float norm = sqrtf(red[0]);
    out[(size_t)b * EMB + t] = v / fmaxf(norm, 1e-12f);
}

extern "C" void kernel_launch(void* const* d_in, const int* in_sizes, int n_in,
                              void* d_out, int out_size) {
    const float* x     = (const float*)d_in[0];
    const float* Wih0  = (const float*)d_in[1];
    const float* Whh0  = (const float*)d_in[2];
    const float* bih0  = (const float*)d_in[3];
    const float* bhh0  = (const float*)d_in[4];
    const float* Whr0  = (const float*)d_in[5];
    const float* Wih1  = (const float*)d_in[6];
    const float* Whh1  = (const float*)d_in[7];
    const float* bih1  = (const float*)d_in[8];
    const float* bhh1  = (const float*)d_in[9];
    const float* Whr1  = (const float*)d_in[10];
    const float* Wih2  = (const float*)d_in[11];
    const float* Whh2  = (const float*)d_in[12];
    const float* bih2  = (const float*)d_in[13];
    const float* bhh2  = (const float*)d_in[14];
    const float* Whr2  = (const float*)d_in[15];
    const float* Wlin  = (const float*)d_in[16];
    const float* blin  = (const float*)d_in[17];
    float* out = (float*)d_out;

    prep_weights<<<2048, 256>>>(Whh0, Whh1, Whh2, Whr0, Whr1, Whr2, Wlin);

    dim3 ggrid(NG / 128, (BSZ * TSTEPS) / 128);

    pre_gemm_kernel<FIN><<<ggrid, 256>>>(x, 0, Wih0, bih0, bhh0);
    lstm_layer_cluster4<<<4 * (BSZ / CNSEQ), RTHR>>>(0);

    pre_gemm_kernel<PROJ><<<ggrid, 256>>>(nullptr, 1, Wih1, bih1, bhh1);
    lstm_layer_cluster4<<<4 * (BSZ / CNSEQ), RTHR>>>(1);

    pre_gemm_kernel<PROJ><<<ggrid, 256>>>(nullptr, 1, Wih2, bih2, bhh2);
    lstm_layer_cluster4<<<4 * (BSZ / CNSEQ), RTHR>>>(2);

    head_kernel<<<BSZ, 256>>>(blin, out);
}

// round 11
// speedup vs baseline: 1.7558x; 1.7558x over previous
#include <cuda_runtime.h>
#include <cooperative_groups.h>
#include <cstdint>
#include <cstddef>

namespace cg = cooperative_groups;

#define BSZ 640
#define TSTEPS 160
#define FIN 80
#define HID 768
#define PROJ 256
#define NG 3072
#define EMB 256
#define NSEQ 10          // sequences per 2-CTA cluster
#define RTHR 384

// ---- device scratch ----
__device__ float  g_pre[(size_t)BSZ * TSTEPS * NG];
__device__ float  g_seq[(size_t)BSZ * TSTEPS * PROJ];
__device__ float2 g_whhT[3 * 128 * HID * 4];   // [l][kp][u][gate] : 32B per (kp,u)
__device__ float2 g_whrT[3 * 384 * PROJ];      // [l][up][p]
__device__ float  g_wlinT[PROJ * EMB];

typedef unsigned long long ull;

__device__ __forceinline__ void fma2(ull& d, ull a, ull b) {
    asm("fma.rn.f32x2 %0, %1, %2, %0;" : "+l"(d) : "l"(a), "l"(b));
}
__device__ __forceinline__ ull pack2(float x, float y) {
    ull r; asm("mov.b64 %0, {%1, %2};" : "=l"(r) : "f"(x), "f"(y)); return r;
}
__device__ __forceinline__ float2 unpack2(ull v) {
    float2 r; asm("mov.b64 {%0, %1}, %2;" : "=f"(r.x), "=f"(r.y) : "l"(v)); return r;
}
__device__ __forceinline__ float sigm_f(float x) { return 1.f / (1.f + __expf(-x)); }
__device__ __forceinline__ float tanh_f(float x) { return 1.f - 2.f / (__expf(2.f * x) + 1.f); }

// ---- weight re-layout ----
// g_whhT[l][kp][u][g] = W_hh[g*HID+u][2kp..2kp+1]  (gate order i,f,g,o preserved)
__global__ void prep_weights(const float* __restrict__ W0, const float* __restrict__ W1,
                             const float* __restrict__ W2,
                             const float* __restrict__ R0, const float* __restrict__ R1,
                             const float* __restrict__ R2,
                             const float* __restrict__ L) {
    const int NWHH = 3 * 128 * HID * 4;
    const int NWHR = 3 * 384 * PROJ;
    const int NWL  = PROJ * EMB;
    const int total = NWHH + NWHR + NWL;
    for (int i = blockIdx.x * blockDim.x + threadIdx.x; i < total; i += gridDim.x * blockDim.x) {
        if (i < NWHH) {
            int l = i / (128 * HID * 4);
            int r = i % (128 * HID * 4);
            int kp = r / (HID * 4);
            int r2 = r % (HID * 4);
            int u = r2 >> 2;
            int g = r2 & 3;
            const float* W = (l == 0) ? W0 : (l == 1) ? W1 : W2;
            size_t j = (size_t)(g * HID + u) * PROJ;
            g_whhT[i] = make_float2(W[j + 2 * kp], W[j + 2 * kp + 1]);
        } else if (i < NWHH + NWHR) {
            int i2 = i - NWHH;
            int l = i2 / (384 * PROJ);
            int r = i2 % (384 * PROJ);
            int p = r % PROJ;
            int up = r / PROJ;
            const float* R = (l == 0) ? R0 : (l == 1) ? R1 : R2;
            g_whrT[i2] = make_float2(R[(size_t)p * HID + 2 * up], R[(size_t)p * HID + 2 * up + 1]);
        } else {
            int i3 = i - NWHH - NWHR;
            int e = i3 % EMB, p = i3 / EMB;
            g_wlinT[i3] = L[(size_t)e * PROJ + p];
        }
    }
}

// ---- input GEMM (unchanged; known-good) ----
template <int K>
__global__ __launch_bounds__(256) void pre_gemm_kernel(const float* __restrict__ xin, int use_seq,
                                                       const float* __restrict__ W,
                                                       const float* __restrict__ bih,
                                                       const float* __restrict__ bhh) {
    const float* A = use_seq ? g_seq : xin;
    __shared__ __align__(16) float As[8][128];
    __shared__ __align__(16) float Bs[8][128];
    const int tid = threadIdx.x;
    const int n0 = blockIdx.x * 128;
    const int m0 = blockIdx.y * 128;
    const int lr = tid >> 1;
    const int lk = (tid & 1) * 4;
    const float* aptr = A + (size_t)(m0 + lr) * K + lk;
    const float* wptr = W + (size_t)(n0 + lr) * K + lk;
    const int tx = tid & 15, ty = tid >> 4;

    ull acc[8][4];
#pragma unroll
    for (int m = 0; m < 8; ++m)
#pragma unroll
        for (int n = 0; n < 4; ++n) acc[m][n] = 0ULL;

    float4 aReg = *(const float4*)aptr;
    float4 bReg = *(const float4*)wptr;
    const int nch = K / 8;

    for (int ch = 0;; ++ch) {
        As[lk + 0][lr] = aReg.x; As[lk + 1][lr] = aReg.y; As[lk + 2][lr] = aReg.z; As[lk + 3][lr] = aReg.w;
        Bs[lk + 0][lr] = bReg.x; Bs[lk + 1][lr] = bReg.y; Bs[lk + 2][lr] = bReg.z; Bs[lk + 3][lr] = bReg.w;
        __syncthreads();
        if (ch + 1 < nch) {
            aptr += 8; wptr += 8;
            aReg = *(const float4*)aptr;
            bReg = *(const float4*)wptr;
        }
#pragma unroll
        for (int k = 0; k < 8; ++k) {
            float4 alo = *(const float4*)&As[k][ty * 8];
            float4 ahi = *(const float4*)&As[k][ty * 8 + 4];
            ulonglong2 bl = *(const ulonglong2*)&Bs[k][tx * 8];
            ulonglong2 bh = *(const ulonglong2*)&Bs[k][tx * 8 + 4];
            ull ap[8];
            ap[0] = pack2(alo.x, alo.x); ap[1] = pack2(alo.y, alo.y);
            ap[2] = pack2(alo.z, alo.z); ap[3] = pack2(alo.w, alo.w);
            ap[4] = pack2(ahi.x, ahi.x); ap[5] = pack2(ahi.y, ahi.y);
            ap[6] = pack2(ahi.z, ahi.z); ap[7] = pack2(ahi.w, ahi.w);
#pragma unroll
            for (int m = 0; m < 8; ++m) {
                fma2(acc[m][0], ap[m], bl.x);
                fma2(acc[m][1], ap[m], bl.y);
                fma2(acc[m][2], ap[m], bh.x);
                fma2(acc[m][3], ap[m], bh.y);
            }
        }
        __syncthreads();
        if (ch + 1 >= nch) break;
    }

    const int col = n0 + tx * 8;
    float bs[8];
#pragma unroll
    for (int i = 0; i < 8; ++i) bs[i] = bih[col + i] + bhh[col + i];
#pragma unroll
    for (int m = 0; m < 8; ++m) {
        const size_t row = (size_t)m0 + ty * 8 + m;
        float* cp = g_pre + row * NG + col;
        float2 v0 = unpack2(acc[m][0]), v1 = unpack2(acc[m][1]);
        float2 v2 = unpack2(acc[m][2]), v3 = unpack2(acc[m][3]);
        *(float4*)cp       = make_float4(v0.x + bs[0], v0.y + bs[1], v1.x + bs[2], v1.y + bs[3]);
        *(float4*)(cp + 4) = make_float4(v2.x + bs[4], v2.y + bs[5], v3.x + bs[6], v3.y + bs[7]);
    }
}

// ---- recurrent: 2-CTA cluster (R3 structure), wide wght loads + reg prefetch ----
__global__ __launch_bounds__(RTHR, 1) __cluster_dims__(2, 1, 1)
void lstm_layer_cluster(int layer) {
    cg::cluster_group clu = cg::this_cluster();
    const unsigned rank = clu.block_rank();
    const unsigned peer = rank ^ 1u;
    const int t = threadIdx.x;
    const int b0 = (blockIdx.x >> 1) * NSEQ;

    __shared__ __align__(16) float h_s[NSEQ][PROJ];
    __shared__ __align__(16) float ht_s[NSEQ][HID];

    const ull* whh_u = reinterpret_cast<const ull*>(g_whhT + (size_t)layer * (128 * HID * 4));
    const ull* whr_u = reinterpret_cast<const ull*>(g_whrT + (size_t)layer * (384 * PROJ));

    for (int i = t; i < NSEQ * PROJ; i += RTHR) (&h_s[0][0])[i] = 0.f;
    float c[NSEQ];
#pragma unroll
    for (int m = 0; m < NSEQ; ++m) c[m] = 0.f;

    const int u = rank * 384 + t;          // this thread's hidden unit
    const int pl = t & 127;
    const int kth = t >> 7;
    const int p = rank * 128 + pl;

    ull* red = reinterpret_cast<ull*>(&ht_s[0][0]);
    float* ht_flat = &ht_s[0][0];
    const float* peer_ht = (const float*)clu.map_shared_rank(ht_flat, peer);
    float* peer_h = (float*)clu.map_shared_rank(&h_s[0][0], peer);

    clu.sync();

    for (int step = 0; step < TSTEPS; ++step) {
        const float* prebase = g_pre + ((size_t)b0 * TSTEPS + step) * NG;

        // ---- gate phase: [kp][u][gate] layout -> 2x LDG.128/kp, prefetch next kp ----
        {
            ull acc[NSEQ][4];
#pragma unroll
            for (int m = 0; m < NSEQ; ++m)
#pragma unroll
                for (int g = 0; g < 4; ++g) acc[m][g] = 0ULL;

            const ull* wp = whh_u + (size_t)u * 4;     // kp = 0
            ulonglong2 w01 = *(const ulonglong2*)(wp);
            ulonglong2 w23 = *(const ulonglong2*)(wp + 2);
            const float* hp = &h_s[0][0];

#pragma unroll 2
            for (int kp = 0; kp < 128; ++kp) {
                ulonglong2 n01, n23;
                if (kp + 1 < 128) {
                    const ull* np = wp + (size_t)4 * HID;
                    n01 = *(const ulonglong2*)(np);
                    n23 = *(const ulonglong2*)(np + 2);
                }
                ull hv[NSEQ];
#pragma unroll
                for (int m = 0; m < NSEQ; ++m)
                    hv[m] = *reinterpret_cast<const ull*>(hp + m * PROJ);
#pragma unroll
                for (int m = 0; m < NSEQ; ++m) {
                    fma2(acc[m][0], hv[m], w01.x);
                    fma2(acc[m][1], hv[m], w01.y);
                    fma2(acc[m][2], hv[m], w23.x);
                    fma2(acc[m][3], hv[m], w23.y);
                }
                wp += (size_t)4 * HID;
                hp += 2;
                w01 = n01; w23 = n23;
            }
#pragma unroll
            for (int m = 0; m < NSEQ; ++m) {
                const float* pm = prebase + (size_t)m * TSTEPS * NG;
                float2 a0 = unpack2(acc[m][0]), a1 = unpack2(acc[m][1]);
                float2 a2 = unpack2(acc[m][2]), a3 = unpack2(acc[m][3]);
                float gi = a0.x + a0.y + pm[u];
                float gf = a1.x + a1.y + pm[HID + u];
                float gg = a2.x + a2.y + pm[2 * HID + u];
                float go = a3.x + a3.y + pm[3 * HID + u];
                float cn = fmaf(sigm_f(gf), c[m], sigm_f(gi) * tanh_f(gg));
                c[m] = cn;
                ht_s[m][u] = sigm_f(go) * tanh_f(cn);
            }
        }
        clu.sync();   // peer's ht half complete + own ht visible

        // ---- fetch peer's ht half via DSMEM ----
        for (int i = t; i < NSEQ * 192; i += RTHR) {
            int m = i / 192, jp = i % 192;
            size_t off = (size_t)m * HID + peer * 384 + 2 * jp;
            *reinterpret_cast<ull*>(ht_flat + off) =
                *reinterpret_cast<const ull*>(peer_ht + off);
        }
        __syncthreads();

        // ---- projection: 3-way k-split ----
        ull pacc[NSEQ];
#pragma unroll
        for (int m = 0; m < NSEQ; ++m) pacc[m] = 0ULL;
        {
            const ull* wr = whr_u + (size_t)(kth * 128) * PROJ + p;
            const float* hb = ht_flat + kth * 256;
#pragma unroll 4
            for (int up = 0; up < 128; ++up) {
                ull wv = wr[(size_t)up * PROJ];
                ull hv[NSEQ];
#pragma unroll
                for (int m = 0; m < NSEQ; ++m)
                    hv[m] = *reinterpret_cast<const ull*>(hb + (size_t)m * HID + 2 * up);
#pragma unroll
                for (int m = 0; m < NSEQ; ++m) fma2(pacc[m], hv[m], wv);
            }
        }
        __syncthreads();   // ht reads done; safe to alias red
        if (kth > 0) {
#pragma unroll
            for (int m = 0; m < NSEQ; ++m) red[((kth - 1) * 128 + pl) * NSEQ + m] = pacc[m];
        }
        __syncthreads();
        if (kth == 0) {
#pragma unroll
            for (int m = 0; m < NSEQ; ++m) {
                float2 a = unpack2(pacc[m]);
                float2 b = unpack2(red[pl * NSEQ + m]);
                float2 d = unpack2(red[(128 + pl) * NSEQ + m]);
                float hnew = a.x + a.y + b.x + b.y + d.x + d.y;
                h_s[m][p] = hnew;
                peer_h[m * PROJ + p] = hnew;
                g_seq[((size_t)(b0 + m) * TSTEPS + step) * PROJ + p] = hnew;
            }
        }
        clu.sync();
    }
}

// ---- head ----
__global__ __launch_bounds__(256) void head_kernel(const float* __restrict__ blin,
                                                   float* __restrict__ out) {
    __shared__ float hsh[PROJ];
    __shared__ float red[256];
    const int b = blockIdx.x, t = threadIdx.x;
    hsh[t] = g_seq[((size_t)b * TSTEPS + TSTEPS - 1) * PROJ + t];
    __syncthreads();
    float acc = 0.f;
#pragma unroll 8
    for (int p = 0; p < PROJ; ++p) acc = fmaf(hsh[p], g_wlinT[p * EMB + t], acc);
    float v = fmaxf(acc + blin[t], 0.f);
    red[t] = v * v;
    __syncthreads();
    for (int s = 128; s > 0; s >>= 1) {
        if (t < s) red[t] += red[t + s];
        __syncthreads();
    }
    float norm = sqrtf(red[0]);
    out[(size_t)b * EMB + t] = v / fmaxf(norm, 1e-12f);
}

extern "C" void kernel_launch(void* const* d_in, const int* in_sizes, int n_in,
                              void* d_out, int out_size) {
    const float* x     = (const float*)d_in[0];
    const float* Wih0  = (const float*)d_in[1];
    const float* Whh0  = (const float*)d_in[2];
    const float* bih0  = (const float*)d_in[3];
    const float* bhh0  = (const float*)d_in[4];
    const float* Whr0  = (const float*)d_in[5];
    const float* Wih1  = (const float*)d_in[6];
    const float* Whh1  = (const float*)d_in[7];
    const float* bih1  = (const float*)d_in[8];
    const float* bhh1  = (const float*)d_in[9];
    const float* Whr1  = (const float*)d_in[10];
    const float* Wih2  = (const float*)d_in[11];
    const float* Whh2  = (const float*)d_in[12];
    const float* bih2  = (const float*)d_in[13];
    const float* bhh2  = (const float*)d_in[14];
    const float* Whr2  = (const float*)d_in[15];
    const float* Wlin  = (const float*)d_in[16];
    const float* blin  = (const float*)d_in[17];
    float* out = (float*)d_out;

    prep_weights<<<2048, 256>>>(Whh0, Whh1, Whh2, Whr0, Whr1, Whr2, Wlin);

    dim3 ggrid(NG / 128, (BSZ * TSTEPS) / 128);

    pre_gemm_kernel<FIN><<<ggrid, 256>>>(x, 0, Wih0, bih0, bhh0);
    lstm_layer_cluster<<<2 * (BSZ / NSEQ), RTHR>>>(0);

    pre_gemm_kernel<PROJ><<<ggrid, 256>>>(nullptr, 1, Wih1, bih1, bhh1);
    lstm_layer_cluster<<<2 * (BSZ / NSEQ), RTHR>>>(1);

    pre_gemm_kernel<PROJ><<<ggrid, 256>>>(nullptr, 1, Wih2, bih2, bhh2);
    lstm_layer_cluster<<<2 * (BSZ / NSEQ), RTHR>>>(2);

    head_kernel<<<BSZ, 256>>>(blin, out);
}